// round 4
// baseline (speedup 1.0000x reference)
#include <cuda_runtime.h>
#include <cuda_fp16.h>
#include <math.h>
#include <cstdint>

#define Bb 16
#define Ss 8192
#define Hh 256

constexpr int CTX_ELEMS = Bb * Hh;
constexpr int ATT_OFF   = CTX_ELEMS;

// -------- scratch --------
__device__ float g_qproj[Bb * Hh];
__device__ float g_maxv[Bb];
__device__ float g_invsum[Bb];
__device__ float g_ctxpart[Bb * 16 * Hh];
__device__ __half g_Bh[Hh * Hh];   // Wk hi, [o][k]
__device__ __half g_Bl[Hh * Hh];   // Wk lo

// ---------------- helpers ----------------
__device__ __forceinline__ uint32_t smem_u32(const void* p) {
    uint32_t a;
    asm("{ .reg .u64 t; cvta.to.shared.u64 t, %1; cvt.u32.u64 %0, t; }" : "=r"(a) : "l"(p));
    return a;
}
__device__ __forceinline__ void ldmx4(uint32_t& r0, uint32_t& r1, uint32_t& r2, uint32_t& r3,
                                      uint32_t addr) {
    asm volatile("ldmatrix.sync.aligned.m8n8.x4.shared.b16 {%0,%1,%2,%3}, [%4];"
                 : "=r"(r0), "=r"(r1), "=r"(r2), "=r"(r3) : "r"(addr));
}
__device__ __forceinline__ void mma_f32(float* d, const uint32_t* a, const uint32_t* b) {
    asm volatile("mma.sync.aligned.m16n8k16.row.col.f32.f16.f16.f32 "
                 "{%0,%1,%2,%3}, {%4,%5,%6,%7}, {%8,%9}, {%0,%1,%2,%3};"
                 : "+f"(d[0]), "+f"(d[1]), "+f"(d[2]), "+f"(d[3])
                 : "r"(a[0]), "r"(a[1]), "r"(a[2]), "r"(a[3]), "r"(b[0]), "r"(b[1]));
}
__device__ __forceinline__ void mma_f16(uint32_t* c, const uint32_t* a, const uint32_t* b) {
    asm volatile("mma.sync.aligned.m16n8k16.row.col.f16.f16.f16.f16 "
                 "{%0,%1}, {%2,%3,%4,%5}, {%6,%7}, {%0,%1};"
                 : "+r"(c[0]), "+r"(c[1])
                 : "r"(a[0]), "r"(a[1]), "r"(a[2]), "r"(a[3]), "r"(b[0]), "r"(b[1]));
}
__device__ __forceinline__ void cp16(uint32_t dst, const void* src) {
    asm volatile("cp.async.cg.shared.global [%0], [%1], 16;" :: "r"(dst), "l"(src) : "memory");
}
#define CP_COMMIT() asm volatile("cp.async.commit_group;" ::: "memory")
#define CP_WAIT0()  asm volatile("cp.async.wait_group 0;" ::: "memory")

__device__ __forceinline__ float tanh_fast(float x) {
    float t, r;
    asm("ex2.approx.f32 %0, %1;" : "=f"(t) : "f"(x * 2.8853900817779268f));
    asm("rcp.approx.f32 %0, %1;" : "=f"(r) : "f"(t + 1.0f));
    return fmaf(-2.0f, r, 1.0f);
}

// ---------------- prep ----------------
__global__ void k_prepB(const float* __restrict__ W) {
    int o = blockIdx.x, k = threadIdx.x;
    float x = W[o * (2 * Hh) + Hh + k];
    __half hi = __float2half_rn(x);
    __half lo = __float2half_rn(x - __half2float(hi));
    g_Bh[o * Hh + k] = hi;
    g_Bl[o * Hh + k] = lo;
}

__global__ void k_qproj(const float* __restrict__ q, const float* __restrict__ W,
                        const float* __restrict__ bvec) {
    __shared__ float sq[Hh];
    int b = blockIdx.x, o = threadIdx.x;
    sq[o] = q[b * Hh + o];
    __syncthreads();
    float s = bvec[o];
    const float* row = W + o * (2 * Hh);
#pragma unroll 8
    for (int h = 0; h < Hh; ++h) s += sq[h] * row[h];
    g_qproj[b * Hh + o] = s;
}

// ---------------- main GEMM kernel ----------------
#define AST 72
// A: 2 buf x 2 split x 18432 ; B: 2 buf x 2 split x 36864
constexpr int AREG = 0;
constexpr int BREG = 73728;
constexpr int QSH_OFF = 221184;
constexpr int VSH_OFF = 222208;
constexpr int SCB_OFF = 223232;
constexpr int SMEM_BYTES = 225280;

__device__ __forceinline__ uint32_t a_off(int buf, int split) {
    return AREG + (buf * 2 + split) * 18432;
}
__device__ __forceinline__ uint32_t b_off(int buf, int split) {
    return BREG + (buf * 2 + split) * 36864;
}

__global__ void __launch_bounds__(512, 1)
k_scores_mma(const float* __restrict__ key, const float* __restrict__ vvec,
             float* __restrict__ out) {
    extern __shared__ char smem[];
    const uint32_t sbase = smem_u32(smem);

    const int tid  = threadIdx.x;
    const int wid  = tid >> 5;
    const int lane = tid & 31;
    const int wr   = wid >> 2;
    const int wc   = wid & 3;
    const int b    = blockIdx.x >> 6;
    const int s0   = (blockIdx.x & 63) * 128;

    float* qsh = (float*)(smem + QSH_OFF);
    float* vsh = (float*)(smem + VSH_OFF);
    float* scb = (float*)(smem + SCB_OFF);

    if (tid < 256) {
        qsh[tid] = g_qproj[b * Hh + tid];
        vsh[tid] = vvec[tid];
    }

    const float* kbase = key + ((long long)(b * Ss + s0)) * Hh;

    float    acc[2][8][4];
    uint32_t accl[2][8][2];
#pragma unroll
    for (int mt = 0; mt < 2; ++mt)
#pragma unroll
        for (int nt = 0; nt < 8; ++nt) {
#pragma unroll
            for (int i = 0; i < 4; ++i) acc[mt][nt][i] = 0.f;
            accl[mt][nt][0] = 0u; accl[mt][nt][1] = 0u;
        }

    const int quad = lane >> 3;
    const int lr   = lane & 7;

    // staging index precompute
    const int sa_k4 = (tid & 15) * 4;        // A: k-subcol
    const int sb_n  = tid >> 3;              // B: n row  (idx>>3 with pass stride)
    const int sb_k8 = (tid & 7) * 8;         // B: k-subcol (halves)

    // ---- stage chunk c into buffer bb ----
    auto stageA = [&](int c, int bb) {
        __half* Ah = (__half*)(smem + a_off(bb, 0));
        __half* Al = (__half*)(smem + a_off(bb, 1));
#pragma unroll
        for (int pass = 0; pass < 4; ++pass) {
            int r = (tid >> 4) + pass * 32;
            float4 x = __ldg((const float4*)(kbase + (long long)r * Hh + c * 64 + sa_k4));
            __half2 h01 = __floats2half2_rn(x.x, x.y);
            __half2 h23 = __floats2half2_rn(x.z, x.w);
            float2 f01 = __half22float2(h01);
            float2 f23 = __half22float2(h23);
            __half2 l01 = __floats2half2_rn(x.x - f01.x, x.y - f01.y);
            __half2 l23 = __floats2half2_rn(x.z - f23.x, x.w - f23.y);
            *(uint2*)(Ah + r * AST + sa_k4) = make_uint2(*(uint32_t*)&h01, *(uint32_t*)&h23);
            *(uint2*)(Al + r * AST + sa_k4) = make_uint2(*(uint32_t*)&l01, *(uint32_t*)&l23);
        }
    };
    auto stageB = [&](int c, int bb) {
        uint32_t dh = sbase + b_off(bb, 0);
        uint32_t dl = sbase + b_off(bb, 1);
#pragma unroll
        for (int pass = 0; pass < 4; ++pass) {
            int n = sb_n + pass * 64;
            uint32_t doff = (uint32_t)(n * AST + sb_k8) * 2u;
            const __half* sh = g_Bh + n * Hh + c * 64 + sb_k8;
            const __half* sl = g_Bl + n * Hh + c * 64 + sb_k8;
            cp16(dh + doff, sh);
            cp16(dl + doff, sl);
        }
        CP_COMMIT();
    };

    // prologue: B0 in flight, A0 converted
    stageB(0, 0);
    stageA(0, 0);

    for (int c = 0; c < 4; ++c) {
        const int buf = c & 1;
        CP_WAIT0();
        __syncthreads();
        if (c < 3) stageB(c + 1, buf ^ 1);

        const uint32_t ah_base = sbase + a_off(buf, 0);
        const uint32_t al_base = sbase + a_off(buf, 1);
        const uint32_t bh_base = sbase + b_off(buf, 0);
        const uint32_t bl_base = sbase + b_off(buf, 1);

#pragma unroll
        for (int ks = 0; ks < 4; ++ks) {
            const int acol = ks * 16 + (quad >> 1) * 8;
            const int bcol = ks * 16 + (quad & 1) * 8;
#pragma unroll
            for (int nh = 0; nh < 2; ++nh) {
                uint32_t bf[4][2];
                // B hi fragments for 4 n8-tiles
#pragma unroll
                for (int ng = 0; ng < 2; ++ng) {
                    int brow = wc * 64 + (nh * 2 + ng) * 16 + (quad >> 1) * 8 + lr;
                    uint32_t r0, r1, r2, r3;
                    ldmx4(r0, r1, r2, r3, bh_base + (uint32_t)(brow * AST + bcol) * 2u);
                    bf[2 * ng][0] = r0; bf[2 * ng][1] = r1;
                    bf[2 * ng + 1][0] = r2; bf[2 * ng + 1][1] = r3;
                }
                uint32_t ah[2][4];
#pragma unroll
                for (int mt = 0; mt < 2; ++mt) {
                    int arow = wr * 32 + mt * 16 + (quad & 1) * 8 + lr;
                    ldmx4(ah[mt][0], ah[mt][1], ah[mt][2], ah[mt][3],
                          ah_base + (uint32_t)(arow * AST + acol) * 2u);
                }
                // hi*hi -> fp32 acc
#pragma unroll
                for (int mt = 0; mt < 2; ++mt)
#pragma unroll
                    for (int j = 0; j < 4; ++j)
                        mma_f32(acc[mt][nh * 4 + j], ah[mt], bf[j]);
                // lo*hi -> fp16 acc
                {
                    uint32_t al[4];
#pragma unroll
                    for (int mt = 0; mt < 2; ++mt) {
                        int arow = wr * 32 + mt * 16 + (quad & 1) * 8 + lr;
                        ldmx4(al[0], al[1], al[2], al[3],
                              al_base + (uint32_t)(arow * AST + acol) * 2u);
#pragma unroll
                        for (int j = 0; j < 4; ++j)
                            mma_f16(accl[mt][nh * 4 + j], al, bf[j]);
                    }
                }
                // hi*lo -> fp16 acc (reuse bf regs)
#pragma unroll
                for (int ng = 0; ng < 2; ++ng) {
                    int brow = wc * 64 + (nh * 2 + ng) * 16 + (quad >> 1) * 8 + lr;
                    uint32_t r0, r1, r2, r3;
                    ldmx4(r0, r1, r2, r3, bl_base + (uint32_t)(brow * AST + bcol) * 2u);
                    bf[2 * ng][0] = r0; bf[2 * ng][1] = r1;
                    bf[2 * ng + 1][0] = r2; bf[2 * ng + 1][1] = r3;
                }
#pragma unroll
                for (int mt = 0; mt < 2; ++mt)
#pragma unroll
                    for (int j = 0; j < 4; ++j)
                        mma_f16(accl[mt][nh * 4 + j], ah[mt], bf[j]);
            }
        }
        if (c < 3) stageA(c + 1, buf ^ 1);
    }

    // ---- epilogue ----
    const int g  = lane >> 2;
    const int tg = lane & 3;
    float part[4] = {0.f, 0.f, 0.f, 0.f};
#pragma unroll
    for (int mt = 0; mt < 2; ++mt)
#pragma unroll
        for (int nt = 0; nt < 8; ++nt) {
            int col0 = wc * 64 + nt * 8 + tg * 2;
            __half2 l0 = *(__half2*)&accl[mt][nt][0];
            __half2 l1 = *(__half2*)&accl[mt][nt][1];
            float lo[4] = {__low2float(l0), __high2float(l0),
                           __low2float(l1), __high2float(l1)};
#pragma unroll
            for (int i = 0; i < 4; ++i) {
                int col = col0 + (i & 1);
                float d = acc[mt][nt][i] + lo[i];
                part[mt * 2 + (i >> 1)] += tanh_fast(d + qsh[col]) * vsh[col];
            }
        }
#pragma unroll
    for (int p = 0; p < 4; ++p) {
        part[p] += __shfl_xor_sync(0xffffffffu, part[p], 1);
        part[p] += __shfl_xor_sync(0xffffffffu, part[p], 2);
    }
    if (tg == 0) {
#pragma unroll
        for (int mt = 0; mt < 2; ++mt)
#pragma unroll
            for (int h = 0; h < 2; ++h) {
                int row = wr * 32 + mt * 16 + h * 8 + g;
                scb[row * 4 + wc] = part[mt * 2 + h];
            }
    }
    __syncthreads();
    if (tid < 128) {
        float s = scb[tid * 4] + scb[tid * 4 + 1] + scb[tid * 4 + 2] + scb[tid * 4 + 3];
        out[ATT_OFF + b * Ss + s0 + tid] = s;
    }
}

// ---------------- softmax stats ----------------
__global__ void k_softmax_stats(const float* __restrict__ out) {
    __shared__ float red[256];
    int b = blockIdx.x, t = threadIdx.x;
    const float* sc = out + ATT_OFF + b * Ss;
    float m = -1e30f;
    for (int i = t; i < Ss; i += 256) m = fmaxf(m, sc[i]);
    red[t] = m; __syncthreads();
    for (int st = 128; st; st >>= 1) {
        if (t < st) red[t] = fmaxf(red[t], red[t + st]);
        __syncthreads();
    }
    float mx = red[0]; __syncthreads();
    float s = 0.f;
    for (int i = t; i < Ss; i += 256) s += expf(sc[i] - mx);
    red[t] = s; __syncthreads();
    for (int st = 128; st; st >>= 1) {
        if (t < st) red[t] += red[t + st];
        __syncthreads();
    }
    if (t == 0) { g_maxv[b] = mx; g_invsum[b] = 1.f / red[0]; }
}

// ---------------- normalize weights + partial context ----------------
#define DCH 512
__global__ void k_context(const float* __restrict__ value, float* __restrict__ out) {
    __shared__ float sw[DCH];
    int b  = blockIdx.x >> 4;
    int ch = blockIdx.x & 15;
    int s0 = ch * DCH;
    int t  = threadIdx.x;
    float mx = g_maxv[b], is = g_invsum[b];
    float* att = out + ATT_OFF + b * Ss;
#pragma unroll
    for (int i = 0; i < 2; ++i) {
        int s = s0 + t + i * 256;
        float w = expf(att[s] - mx) * is;
        att[s] = w;
        sw[t + i * 256] = w;
    }
    __syncthreads();
    const float* vb = value + ((long long)b * Ss + s0) * Hh + t;
    float a0 = 0.f, a1 = 0.f, a2 = 0.f, a3 = 0.f;
#pragma unroll 2
    for (int s = 0; s < DCH; s += 4) {
        a0 += sw[s]     * __ldg(vb + (long long)(s)     * Hh);
        a1 += sw[s + 1] * __ldg(vb + (long long)(s + 1) * Hh);
        a2 += sw[s + 2] * __ldg(vb + (long long)(s + 2) * Hh);
        a3 += sw[s + 3] * __ldg(vb + (long long)(s + 3) * Hh);
    }
    g_ctxpart[(b * 16 + ch) * Hh + t] = (a0 + a1) + (a2 + a3);
}

__global__ void k_reduce_ctx(float* __restrict__ out) {
    int b = blockIdx.x, t = threadIdx.x;
    float s = 0.f;
#pragma unroll
    for (int c = 0; c < 16; ++c) s += g_ctxpart[(b * 16 + c) * Hh + t];
    out[b * Hh + t] = s;
}

// ---------------- launch ----------------
extern "C" void kernel_launch(void* const* d_in, const int* in_sizes, int n_in,
                              void* d_out, int out_size) {
    const float* query  = (const float*)d_in[0];
    const float* key    = (const float*)d_in[1];
    const float* value  = (const float*)d_in[2];
    const float* W_attn = (const float*)d_in[3];
    const float* b_attn = (const float*)d_in[4];
    const float* v      = (const float*)d_in[5];
    float* out = (float*)d_out;

    cudaFuncSetAttribute(k_scores_mma, cudaFuncAttributeMaxDynamicSharedMemorySize, SMEM_BYTES);

    k_prepB<<<256, 256>>>(W_attn);
    k_qproj<<<Bb, Hh>>>(query, W_attn, b_attn);
    k_scores_mma<<<Bb * 64, 512, SMEM_BYTES>>>(key, v, out);
    k_softmax_stats<<<Bb, 256>>>(out);
    k_context<<<Bb * 16, 256>>>(value, out);
    k_reduce_ctx<<<Bb, Hh>>>(out);
}

// round 5
// speedup vs baseline: 1.1179x; 1.1179x over previous
#include <cuda_runtime.h>
#include <cuda_fp16.h>
#include <math.h>
#include <cstdint>

#define Bb 16
#define Ss 8192
#define Hh 256

constexpr int CTX_ELEMS = Bb * Hh;
constexpr int ATT_OFF   = CTX_ELEMS;

// -------- scratch --------
__device__ float g_qproj[Bb * Hh];
__device__ float g_maxv[Bb];
__device__ float g_invsum[Bb];
__device__ float g_ctxpart[Bb * 32 * Hh];
__device__ __half g_Bh[Hh * Hh];   // Wk hi, [o][k]
__device__ __half g_Bl[Hh * Hh];   // Wk lo

// ---------------- helpers ----------------
__device__ __forceinline__ uint32_t smem_u32(const void* p) {
    uint32_t a;
    asm("{ .reg .u64 t; cvta.to.shared.u64 t, %1; cvt.u32.u64 %0, t; }" : "=r"(a) : "l"(p));
    return a;
}
__device__ __forceinline__ void ldmx4(uint32_t& r0, uint32_t& r1, uint32_t& r2, uint32_t& r3,
                                      uint32_t addr) {
    asm volatile("ldmatrix.sync.aligned.m8n8.x4.shared.b16 {%0,%1,%2,%3}, [%4];"
                 : "=r"(r0), "=r"(r1), "=r"(r2), "=r"(r3) : "r"(addr));
}
__device__ __forceinline__ void mma_f32(float* d, const uint32_t* a, const uint32_t* b) {
    asm volatile("mma.sync.aligned.m16n8k16.row.col.f32.f16.f16.f32 "
                 "{%0,%1,%2,%3}, {%4,%5,%6,%7}, {%8,%9}, {%0,%1,%2,%3};"
                 : "+f"(d[0]), "+f"(d[1]), "+f"(d[2]), "+f"(d[3])
                 : "r"(a[0]), "r"(a[1]), "r"(a[2]), "r"(a[3]), "r"(b[0]), "r"(b[1]));
}
__device__ __forceinline__ void cp16(uint32_t dst, const void* src) {
    asm volatile("cp.async.cg.shared.global [%0], [%1], 16;" :: "r"(dst), "l"(src) : "memory");
}
#define CP_COMMIT() asm volatile("cp.async.commit_group;" ::: "memory")
#define CP_WAIT0()  asm volatile("cp.async.wait_group 0;" ::: "memory")

__device__ __forceinline__ float tanh_fast(float x) {
    float t, r;
    asm("ex2.approx.f32 %0, %1;" : "=f"(t) : "f"(x * 2.8853900817779268f));
    asm("rcp.approx.f32 %0, %1;" : "=f"(r) : "f"(t + 1.0f));
    return fmaf(-2.0f, r, 1.0f);
}

// ---------------- prep ----------------
__global__ void k_prepB(const float* __restrict__ W) {
    int o = blockIdx.x, k = threadIdx.x;
    float x = W[o * (2 * Hh) + Hh + k];
    __half hi = __float2half_rn(x);
    __half lo = __float2half_rn(x - __half2float(hi));
    g_Bh[o * Hh + k] = hi;
    g_Bl[o * Hh + k] = lo;
}

__global__ void k_qproj(const float* __restrict__ q, const float* __restrict__ W,
                        const float* __restrict__ bvec) {
    __shared__ float sq[Hh];
    int b = blockIdx.x, o = threadIdx.x;
    sq[o] = q[b * Hh + o];
    __syncthreads();
    float s = bvec[o];
    const float* row = W + o * (2 * Hh);
#pragma unroll 8
    for (int h = 0; h < Hh; ++h) s += sq[h] * row[h];
    g_qproj[b * Hh + o] = s;
}

// ---------------- main GEMM kernel ----------------
#define AST 72
constexpr int AREG = 0;          // A: 2 buf x 2 split x 18432 = 73728
constexpr int BREG = 73728;      // B: 2 buf x 2 split x 36864 = 147456
constexpr int QSH_OFF = 221184;
constexpr int VSH_OFF = 222208;
constexpr int SCB_OFF = 223232;
constexpr int SMEM_BYTES = 225280;

__device__ __forceinline__ uint32_t a_off(int buf, int split) {
    return AREG + (buf * 2 + split) * 18432;
}
__device__ __forceinline__ uint32_t b_off(int buf, int split) {
    return BREG + (buf * 2 + split) * 36864;
}

__global__ void __launch_bounds__(512, 1)
k_scores_mma(const float* __restrict__ key, const float* __restrict__ vvec,
             float* __restrict__ out) {
    extern __shared__ char smem[];
    const uint32_t sbase = smem_u32(smem);

    const int tid  = threadIdx.x;
    const int wid  = tid >> 5;
    const int lane = tid & 31;
    const int wr   = wid >> 2;
    const int wc   = wid & 3;
    const int b    = blockIdx.x >> 6;
    const int s0   = (blockIdx.x & 63) * 128;

    float* qsh = (float*)(smem + QSH_OFF);
    float* vsh = (float*)(smem + VSH_OFF);
    float* scb = (float*)(smem + SCB_OFF);

    if (tid < 256) {
        qsh[tid] = g_qproj[b * Hh + tid];
        vsh[tid] = vvec[tid];
    }

    const float* kbase = key + ((long long)(b * Ss + s0)) * Hh;

    float acc[2][8][4];
#pragma unroll
    for (int mt = 0; mt < 2; ++mt)
#pragma unroll
        for (int nt = 0; nt < 8; ++nt)
#pragma unroll
            for (int i = 0; i < 4; ++i) acc[mt][nt][i] = 0.f;

    const int quad = lane >> 3;
    const int lr   = lane & 7;

    const int sa_r0 = tid >> 4;               // A: row base (pass stride 32)
    const int sa_k4 = (tid & 15) * 4;         // A: k-subcol
    const int sb_n  = tid >> 3;               // B: n row (pass stride 64)
    const int sb_k8 = (tid & 7) * 8;          // B: k-subcol

    float4 pA[4];   // early-loaded A chunk (held across MMA loop)

    auto ldA = [&](int c) {
#pragma unroll
        for (int pass = 0; pass < 4; ++pass) {
            int r = sa_r0 + pass * 32;
            pA[pass] = __ldg((const float4*)(kbase + (long long)r * Hh + c * 64 + sa_k4));
        }
    };
    auto stA = [&](int bb) {
        __half* Ah = (__half*)(smem + a_off(bb, 0));
        __half* Al = (__half*)(smem + a_off(bb, 1));
#pragma unroll
        for (int pass = 0; pass < 4; ++pass) {
            int r = sa_r0 + pass * 32;
            float4 x = pA[pass];
            __half2 h01 = __floats2half2_rn(x.x, x.y);
            __half2 h23 = __floats2half2_rn(x.z, x.w);
            float2 f01 = __half22float2(h01);
            float2 f23 = __half22float2(h23);
            __half2 l01 = __floats2half2_rn(x.x - f01.x, x.y - f01.y);
            __half2 l23 = __floats2half2_rn(x.z - f23.x, x.w - f23.y);
            *(uint2*)(Ah + r * AST + sa_k4) = make_uint2(*(uint32_t*)&h01, *(uint32_t*)&h23);
            *(uint2*)(Al + r * AST + sa_k4) = make_uint2(*(uint32_t*)&l01, *(uint32_t*)&l23);
        }
    };
    auto stageB = [&](int c, int bb) {
        uint32_t dh = sbase + b_off(bb, 0);
        uint32_t dl = sbase + b_off(bb, 1);
#pragma unroll
        for (int pass = 0; pass < 4; ++pass) {
            int n = sb_n + pass * 64;
            uint32_t doff = (uint32_t)(n * AST + sb_k8) * 2u;
            cp16(dh + doff, g_Bh + n * Hh + c * 64 + sb_k8);
            cp16(dl + doff, g_Bl + n * Hh + c * 64 + sb_k8);
        }
        CP_COMMIT();
    };

    // prologue
    stageB(0, 0);
    ldA(0);
    stA(0);
    CP_WAIT0();
    __syncthreads();

    for (int c = 0; c < 4; ++c) {
        const int buf = c & 1;
        if (c < 3) {
            stageB(c + 1, buf ^ 1);   // async copy in flight under MMAs
            ldA(c + 1);               // LDG latency hidden under MMAs
        }

        const uint32_t ah_base = sbase + a_off(buf, 0);
        const uint32_t al_base = sbase + a_off(buf, 1);
        const uint32_t bh_base = sbase + b_off(buf, 0);
        const uint32_t bl_base = sbase + b_off(buf, 1);

#pragma unroll
        for (int ks = 0; ks < 4; ++ks) {
            const int acol = ks * 16 + (quad >> 1) * 8;
            const int bcol = ks * 16 + (quad & 1) * 8;

            uint32_t bf[8][2];
#pragma unroll
            for (int ng = 0; ng < 4; ++ng) {
                int brow = wc * 64 + ng * 16 + (quad >> 1) * 8 + lr;
                uint32_t r0, r1, r2, r3;
                ldmx4(r0, r1, r2, r3, bh_base + (uint32_t)(brow * AST + bcol) * 2u);
                bf[2 * ng][0] = r0; bf[2 * ng][1] = r1;
                bf[2 * ng + 1][0] = r2; bf[2 * ng + 1][1] = r3;
            }
            uint32_t ah[2][4];
#pragma unroll
            for (int mt = 0; mt < 2; ++mt) {
                int arow = wr * 32 + mt * 16 + (quad & 1) * 8 + lr;
                ldmx4(ah[mt][0], ah[mt][1], ah[mt][2], ah[mt][3],
                      ah_base + (uint32_t)(arow * AST + acol) * 2u);
            }
            // hi*hi
#pragma unroll
            for (int mt = 0; mt < 2; ++mt)
#pragma unroll
                for (int nt = 0; nt < 8; ++nt)
                    mma_f32(acc[mt][nt], ah[mt], bf[nt]);
            // lo*hi
            {
                uint32_t al[4];
#pragma unroll
                for (int mt = 0; mt < 2; ++mt) {
                    int arow = wr * 32 + mt * 16 + (quad & 1) * 8 + lr;
                    ldmx4(al[0], al[1], al[2], al[3],
                          al_base + (uint32_t)(arow * AST + acol) * 2u);
#pragma unroll
                    for (int nt = 0; nt < 8; ++nt)
                        mma_f32(acc[mt][nt], al, bf[nt]);
                }
            }
            // hi*lo (reuse bf regs)
#pragma unroll
            for (int ng = 0; ng < 4; ++ng) {
                int brow = wc * 64 + ng * 16 + (quad >> 1) * 8 + lr;
                uint32_t r0, r1, r2, r3;
                ldmx4(r0, r1, r2, r3, bl_base + (uint32_t)(brow * AST + bcol) * 2u);
                bf[2 * ng][0] = r0; bf[2 * ng][1] = r1;
                bf[2 * ng + 1][0] = r2; bf[2 * ng + 1][1] = r3;
            }
#pragma unroll
            for (int mt = 0; mt < 2; ++mt)
#pragma unroll
                for (int nt = 0; nt < 8; ++nt)
                    mma_f32(acc[mt][nt], ah[mt], bf[nt]);
        }

        if (c < 3) stA(buf ^ 1);
        CP_WAIT0();
        __syncthreads();
    }

    // ---- epilogue ----
    const int g  = lane >> 2;
    const int tg = lane & 3;
    float part[4] = {0.f, 0.f, 0.f, 0.f};
#pragma unroll
    for (int mt = 0; mt < 2; ++mt)
#pragma unroll
        for (int nt = 0; nt < 8; ++nt) {
            int col0 = wc * 64 + nt * 8 + tg * 2;
#pragma unroll
            for (int i = 0; i < 4; ++i) {
                int col = col0 + (i & 1);
                part[mt * 2 + (i >> 1)] += tanh_fast(acc[mt][nt][i] + qsh[col]) * vsh[col];
            }
        }
#pragma unroll
    for (int p = 0; p < 4; ++p) {
        part[p] += __shfl_xor_sync(0xffffffffu, part[p], 1);
        part[p] += __shfl_xor_sync(0xffffffffu, part[p], 2);
    }
    if (tg == 0) {
#pragma unroll
        for (int mt = 0; mt < 2; ++mt)
#pragma unroll
            for (int h = 0; h < 2; ++h) {
                int row = wr * 32 + mt * 16 + h * 8 + g;
                scb[row * 4 + wc] = part[mt * 2 + h];
            }
    }
    __syncthreads();
    if (tid < 128) {
        float s = scb[tid * 4] + scb[tid * 4 + 1] + scb[tid * 4 + 2] + scb[tid * 4 + 3];
        out[ATT_OFF + b * Ss + s0 + tid] = s;
    }
}

// ---------------- softmax stats ----------------
__global__ void k_softmax_stats(const float* __restrict__ out) {
    __shared__ float red[1024];
    int b = blockIdx.x, t = threadIdx.x;
    const float* sc = out + ATT_OFF + b * Ss;
    float4 x0 = __ldg((const float4*)(sc) + t);
    float4 x1 = __ldg((const float4*)(sc) + t + 1024);
    float m = fmaxf(fmaxf(fmaxf(x0.x, x0.y), fmaxf(x0.z, x0.w)),
                    fmaxf(fmaxf(x1.x, x1.y), fmaxf(x1.z, x1.w)));
    red[t] = m; __syncthreads();
    for (int st = 512; st; st >>= 1) {
        if (t < st) red[t] = fmaxf(red[t], red[t + st]);
        __syncthreads();
    }
    float mx = red[0]; __syncthreads();
    float s = expf(x0.x - mx) + expf(x0.y - mx) + expf(x0.z - mx) + expf(x0.w - mx)
            + expf(x1.x - mx) + expf(x1.y - mx) + expf(x1.z - mx) + expf(x1.w - mx);
    red[t] = s; __syncthreads();
    for (int st = 512; st; st >>= 1) {
        if (t < st) red[t] += red[t + st];
        __syncthreads();
    }
    if (t == 0) { g_maxv[b] = mx; g_invsum[b] = 1.f / red[0]; }
}

// ---------------- normalize weights + partial context ----------------
#define DCH 256
__global__ void k_context(const float* __restrict__ value, float* __restrict__ out) {
    __shared__ float sw[DCH];
    __shared__ float4 red[256];
    int b  = blockIdx.x >> 5;
    int ch = blockIdx.x & 31;
    int s0 = ch * DCH;
    int t  = threadIdx.x;          // 256
    float mx = g_maxv[b], is = g_invsum[b];
    float* att = out + ATT_OFF + b * Ss;
    {
        int s = s0 + t;
        float w = expf(att[s] - mx) * is;
        att[s] = w;
        sw[t] = w;
    }
    __syncthreads();

    const int c4 = (t & 63) * 4;   // column group
    const int rg = t >> 6;         // row group 0..3 (64 rows each)
    const float* vb = value + ((long long)(b * Ss + s0 + rg * 64)) * Hh + c4;
    const float* swp = sw + rg * 64;

    float4 a = make_float4(0.f, 0.f, 0.f, 0.f);
#pragma unroll 4
    for (int r = 0; r < 64; ++r) {
        float w = swp[r];
        float4 v4 = __ldg((const float4*)(vb + (long long)r * Hh));
        a.x += w * v4.x; a.y += w * v4.y; a.z += w * v4.z; a.w += w * v4.w;
    }
    red[t] = a;
    __syncthreads();
    if (rg == 0) {
        float4 r1 = red[t + 64], r2 = red[t + 128], r3 = red[t + 192];
        a.x += r1.x + r2.x + r3.x;
        a.y += r1.y + r2.y + r3.y;
        a.z += r1.z + r2.z + r3.z;
        a.w += r1.w + r2.w + r3.w;
        *(float4*)(g_ctxpart + ((b * 32 + ch) * Hh + c4)) = a;
    }
}

__global__ void k_reduce_ctx(float* __restrict__ out) {
    int b = blockIdx.x, t = threadIdx.x;
    float s = 0.f;
#pragma unroll
    for (int c = 0; c < 32; ++c) s += g_ctxpart[(b * 32 + c) * Hh + t];
    out[b * Hh + t] = s;
}

// ---------------- launch ----------------
extern "C" void kernel_launch(void* const* d_in, const int* in_sizes, int n_in,
                              void* d_out, int out_size) {
    const float* query  = (const float*)d_in[0];
    const float* key    = (const float*)d_in[1];
    const float* value  = (const float*)d_in[2];
    const float* W_attn = (const float*)d_in[3];
    const float* b_attn = (const float*)d_in[4];
    const float* v      = (const float*)d_in[5];
    float* out = (float*)d_out;

    cudaFuncSetAttribute(k_scores_mma, cudaFuncAttributeMaxDynamicSharedMemorySize, SMEM_BYTES);

    k_prepB<<<256, 256>>>(W_attn);
    k_qproj<<<Bb, Hh>>>(query, W_attn, b_attn);
    k_scores_mma<<<Bb * 64, 512, SMEM_BYTES>>>(key, v, out);
    k_softmax_stats<<<Bb, 1024>>>(out);
    k_context<<<Bb * 32, 256>>>(value, out);
    k_reduce_ctx<<<Bb, Hh>>>(out);
}

// round 6
// speedup vs baseline: 1.1622x; 1.0396x over previous
#include <cuda_runtime.h>
#include <cuda_fp16.h>
#include <math.h>
#include <cstdint>

#define Bb 16
#define Ss 8192
#define Hh 256

constexpr int CTX_ELEMS = Bb * Hh;
constexpr int ATT_OFF   = CTX_ELEMS;
constexpr int NTILES    = Bb * 64;     // 1024
constexpr int NCTA      = 148;

// -------- scratch --------
__device__ float g_qproj[Bb * Hh];
__device__ float g_maxv[Bb];
__device__ float g_invsum[Bb];
__device__ float g_ctxpart[Bb * 32 * Hh];
__device__ float g_blkmax[NTILES];
__device__ float g_blksum[NTILES];
__device__ __half g_Bh[Hh * Hh];   // Wk hi, [o][k]
__device__ __half g_Bl[Hh * Hh];   // Wk lo

// ---------------- helpers ----------------
__device__ __forceinline__ uint32_t smem_u32(const void* p) {
    uint32_t a;
    asm("{ .reg .u64 t; cvta.to.shared.u64 t, %1; cvt.u32.u64 %0, t; }" : "=r"(a) : "l"(p));
    return a;
}
__device__ __forceinline__ void ldmx4(uint32_t& r0, uint32_t& r1, uint32_t& r2, uint32_t& r3,
                                      uint32_t addr) {
    asm volatile("ldmatrix.sync.aligned.m8n8.x4.shared.b16 {%0,%1,%2,%3}, [%4];"
                 : "=r"(r0), "=r"(r1), "=r"(r2), "=r"(r3) : "r"(addr));
}
__device__ __forceinline__ void mma_f32(float* d, const uint32_t* a, const uint32_t* b) {
    asm volatile("mma.sync.aligned.m16n8k16.row.col.f32.f16.f16.f32 "
                 "{%0,%1,%2,%3}, {%4,%5,%6,%7}, {%8,%9}, {%0,%1,%2,%3};"
                 : "+f"(d[0]), "+f"(d[1]), "+f"(d[2]), "+f"(d[3])
                 : "r"(a[0]), "r"(a[1]), "r"(a[2]), "r"(a[3]), "r"(b[0]), "r"(b[1]));
}
__device__ __forceinline__ void cp16(uint32_t dst, const void* src) {
    asm volatile("cp.async.cg.shared.global [%0], [%1], 16;" :: "r"(dst), "l"(src) : "memory");
}
#define CP_COMMIT() asm volatile("cp.async.commit_group;" ::: "memory")
#define CP_WAIT0()  asm volatile("cp.async.wait_group 0;" ::: "memory")

__device__ __forceinline__ float tanh_fast(float x) {
    float t, r;
    asm("ex2.approx.f32 %0, %1;" : "=f"(t) : "f"(x * 2.8853900817779268f));
    asm("rcp.approx.f32 %0, %1;" : "=f"(r) : "f"(t + 1.0f));
    return fmaf(-2.0f, r, 1.0f);
}

// ---------------- prep: Wk split + q projection, one launch ----------------
__global__ void k_prep(const float* __restrict__ W, const float* __restrict__ q,
                       const float* __restrict__ bvec) {
    if (blockIdx.x < 256) {
        int o = blockIdx.x, k = threadIdx.x;
        float x = W[o * (2 * Hh) + Hh + k];
        __half hi = __float2half_rn(x);
        __half lo = __float2half_rn(x - __half2float(hi));
        g_Bh[o * Hh + k] = hi;
        g_Bl[o * Hh + k] = lo;
    } else {
        __shared__ float sq[Hh];
        int b = blockIdx.x - 256, o = threadIdx.x;
        sq[o] = q[b * Hh + o];
        __syncthreads();
        float s = bvec[o];
        const float* row = W + o * (2 * Hh);
#pragma unroll 8
        for (int h = 0; h < Hh; ++h) s += sq[h] * row[h];
        g_qproj[b * Hh + o] = s;
    }
}

// ---------------- main persistent GEMM kernel ----------------
#define AST 72
constexpr int AREG = 0;          // A: 2 buf x 2 split x 18432 = 73728
constexpr int BREG = 73728;      // B: 2 buf x 2 split x 36864 = 147456
constexpr int QSH_OFF = 221184;  // 256 f
constexpr int VSH_OFF = 222208;  // 256 f
constexpr int SCB_OFF = 223232;  // 512 f
constexpr int SMEM_BYTES = 225280;

__device__ __forceinline__ uint32_t a_off(int buf, int split) {
    return AREG + (buf * 2 + split) * 18432;
}
__device__ __forceinline__ uint32_t b_off(int buf, int split) {
    return BREG + (buf * 2 + split) * 36864;
}

__global__ void __launch_bounds__(512, 1)
k_scores_mma(const float* __restrict__ key, const float* __restrict__ vvec,
             float* __restrict__ out) {
    extern __shared__ char smem[];
    const uint32_t sbase = smem_u32(smem);

    const int tid  = threadIdx.x;
    const int wid  = tid >> 5;
    const int lane = tid & 31;
    const int wr   = wid >> 2;
    const int wc   = wid & 3;
    const int bid  = blockIdx.x;

    float* qsh = (float*)(smem + QSH_OFF);
    float* vsh = (float*)(smem + VSH_OFF);
    float* scb = (float*)(smem + SCB_OFF);

    if (tid < 256) vsh[tid] = vvec[tid];

    float acc[2][8][4];
#pragma unroll
    for (int mt = 0; mt < 2; ++mt)
#pragma unroll
        for (int nt = 0; nt < 8; ++nt)
#pragma unroll
            for (int i = 0; i < 4; ++i) acc[mt][nt][i] = 0.f;

    const int quad = lane >> 3;
    const int lr   = lane & 7;

    const int sa_r0 = tid >> 4;
    const int sa_k4 = (tid & 15) * 4;
    const int sb_n  = tid >> 3;
    const int sb_k8 = (tid & 7) * 8;

    float4 pA[4];

    auto ldA = [&](int tile, int c) {
        const float* kb = key + ((long long)((tile >> 6) * Ss + (tile & 63) * 128)) * Hh;
#pragma unroll
        for (int pass = 0; pass < 4; ++pass) {
            int r = sa_r0 + pass * 32;
            pA[pass] = __ldg((const float4*)(kb + (long long)r * Hh + c * 64 + sa_k4));
        }
    };
    auto stA = [&](int bb) {
        __half* Ah = (__half*)(smem + a_off(bb, 0));
        __half* Al = (__half*)(smem + a_off(bb, 1));
#pragma unroll
        for (int pass = 0; pass < 4; ++pass) {
            int r = sa_r0 + pass * 32;
            float4 x = pA[pass];
            __half2 h01 = __floats2half2_rn(x.x, x.y);
            __half2 h23 = __floats2half2_rn(x.z, x.w);
            float2 f01 = __half22float2(h01);
            float2 f23 = __half22float2(h23);
            __half2 l01 = __floats2half2_rn(x.x - f01.x, x.y - f01.y);
            __half2 l23 = __floats2half2_rn(x.z - f23.x, x.w - f23.y);
            *(uint2*)(Ah + r * AST + sa_k4) = make_uint2(*(uint32_t*)&h01, *(uint32_t*)&h23);
            *(uint2*)(Al + r * AST + sa_k4) = make_uint2(*(uint32_t*)&l01, *(uint32_t*)&l23);
        }
    };
    auto stageB = [&](int c, int bb) {
        uint32_t dh = sbase + b_off(bb, 0);
        uint32_t dl = sbase + b_off(bb, 1);
#pragma unroll
        for (int pass = 0; pass < 4; ++pass) {
            int n = sb_n + pass * 64;
            uint32_t doff = (uint32_t)(n * AST + sb_k8) * 2u;
            cp16(dh + doff, g_Bh + n * Hh + c * 64 + sb_k8);
            cp16(dl + doff, g_Bl + n * Hh + c * 64 + sb_k8);
        }
        CP_COMMIT();
    };

    const int ntile = (NTILES - bid + NCTA - 1) / NCTA;
    const int nseq  = ntile * 4;

    // prologue: seq 0 = (tile bid, chunk 0)
    stageB(0, 0);
    ldA(bid, 0);
    stA(0);
    CP_WAIT0();
    __syncthreads();

    for (int seq = 0; seq < nseq; ++seq) {
        const int c    = seq & 3;
        const int buf  = seq & 1;
        const int tile = bid + (seq >> 2) * NCTA;

        if (seq + 1 < nseq) {
            stageB((seq + 1) & 3, buf ^ 1);
            ldA(bid + ((seq + 1) >> 2) * NCTA, (seq + 1) & 3);
        }

        const uint32_t ah_base = sbase + a_off(buf, 0);
        const uint32_t al_base = sbase + a_off(buf, 1);
        const uint32_t bh_base = sbase + b_off(buf, 0);
        const uint32_t bl_base = sbase + b_off(buf, 1);

#pragma unroll
        for (int ks = 0; ks < 4; ++ks) {
            const int acol = ks * 16 + (quad >> 1) * 8;
            const int bcol = ks * 16 + (quad & 1) * 8;

            uint32_t bf[8][2];
#pragma unroll
            for (int ng = 0; ng < 4; ++ng) {
                int brow = wc * 64 + ng * 16 + (quad >> 1) * 8 + lr;
                uint32_t r0, r1, r2, r3;
                ldmx4(r0, r1, r2, r3, bh_base + (uint32_t)(brow * AST + bcol) * 2u);
                bf[2 * ng][0] = r0; bf[2 * ng][1] = r1;
                bf[2 * ng + 1][0] = r2; bf[2 * ng + 1][1] = r3;
            }
            uint32_t ah[2][4];
#pragma unroll
            for (int mt = 0; mt < 2; ++mt) {
                int arow = wr * 32 + mt * 16 + (quad & 1) * 8 + lr;
                ldmx4(ah[mt][0], ah[mt][1], ah[mt][2], ah[mt][3],
                      ah_base + (uint32_t)(arow * AST + acol) * 2u);
            }
#pragma unroll
            for (int mt = 0; mt < 2; ++mt)
#pragma unroll
                for (int nt = 0; nt < 8; ++nt)
                    mma_f32(acc[mt][nt], ah[mt], bf[nt]);
            {
                uint32_t al[4];
#pragma unroll
                for (int mt = 0; mt < 2; ++mt) {
                    int arow = wr * 32 + mt * 16 + (quad & 1) * 8 + lr;
                    ldmx4(al[0], al[1], al[2], al[3],
                          al_base + (uint32_t)(arow * AST + acol) * 2u);
#pragma unroll
                    for (int nt = 0; nt < 8; ++nt)
                        mma_f32(acc[mt][nt], al, bf[nt]);
                }
            }
#pragma unroll
            for (int ng = 0; ng < 4; ++ng) {
                int brow = wc * 64 + ng * 16 + (quad >> 1) * 8 + lr;
                uint32_t r0, r1, r2, r3;
                ldmx4(r0, r1, r2, r3, bl_base + (uint32_t)(brow * AST + bcol) * 2u);
                bf[2 * ng][0] = r0; bf[2 * ng][1] = r1;
                bf[2 * ng + 1][0] = r2; bf[2 * ng + 1][1] = r3;
            }
#pragma unroll
            for (int mt = 0; mt < 2; ++mt)
#pragma unroll
                for (int nt = 0; nt < 8; ++nt)
                    mma_f32(acc[mt][nt], ah[mt], bf[nt]);
        }

        if (seq + 1 < nseq) stA(buf ^ 1);
        CP_WAIT0();
        __syncthreads();

        if (c == 3) {
            // ---- epilogue for this tile ----
            const int b  = tile >> 6;
            const int s0 = (tile & 63) * 128;

            if (tid < 256) qsh[tid] = __ldg(g_qproj + b * Hh + tid);
            __syncthreads();

            const int g  = lane >> 2;
            const int tg = lane & 3;
            float part[4] = {0.f, 0.f, 0.f, 0.f};
#pragma unroll
            for (int mt = 0; mt < 2; ++mt)
#pragma unroll
                for (int nt = 0; nt < 8; ++nt) {
                    int col0 = wc * 64 + nt * 8 + tg * 2;
                    float2 qp = *(float2*)(qsh + col0);
                    float2 vp = *(float2*)(vsh + col0);
#pragma unroll
                    for (int i = 0; i < 4; ++i) {
                        float qv = (i & 1) ? qp.y : qp.x;
                        float vv = (i & 1) ? vp.y : vp.x;
                        part[mt * 2 + (i >> 1)] += tanh_fast(acc[mt][nt][i] + qv) * vv;
                    }
                }
#pragma unroll
            for (int p = 0; p < 4; ++p) {
                part[p] += __shfl_xor_sync(0xffffffffu, part[p], 1);
                part[p] += __shfl_xor_sync(0xffffffffu, part[p], 2);
            }
            if (tg == 0) {
#pragma unroll
                for (int mt = 0; mt < 2; ++mt)
#pragma unroll
                    for (int h = 0; h < 2; ++h) {
                        int row = wr * 32 + mt * 16 + h * 8 + g;
                        scb[row * 4 + wc] = part[mt * 2 + h];
                    }
            }
            __syncthreads();
            float s = 0.f;
            if (tid < 128) {
                s = scb[tid * 4] + scb[tid * 4 + 1] + scb[tid * 4 + 2] + scb[tid * 4 + 3];
                out[ATT_OFF + b * Ss + s0 + tid] = s;
            }
            __syncthreads();
            if (tid < 128) scb[tid] = s;
            __syncthreads();
            if (tid < 32) {
                float m = fmaxf(fmaxf(scb[tid], scb[tid + 32]),
                                fmaxf(scb[tid + 64], scb[tid + 96]));
#pragma unroll
                for (int off = 16; off; off >>= 1)
                    m = fmaxf(m, __shfl_xor_sync(0xffffffffu, m, off));
                float e = expf(scb[tid] - m) + expf(scb[tid + 32] - m)
                        + expf(scb[tid + 64] - m) + expf(scb[tid + 96] - m);
#pragma unroll
                for (int off = 16; off; off >>= 1)
                    e += __shfl_xor_sync(0xffffffffu, e, off);
                if (lane == 0) { g_blkmax[tile] = m; g_blksum[tile] = e; }
            }
            // reset accumulators for next tile
#pragma unroll
            for (int mt = 0; mt < 2; ++mt)
#pragma unroll
                for (int nt = 0; nt < 8; ++nt)
#pragma unroll
                    for (int i = 0; i < 4; ++i) acc[mt][nt][i] = 0.f;
        }
    }
}

// ---------------- softmax combine (phase 2) ----------------
__global__ void k_softmax_combine() {
    __shared__ float sm[64], ss[64];
    int b = blockIdx.x, t = threadIdx.x;   // 64 threads
    float m = g_blkmax[b * 64 + t];
    sm[t] = m; __syncthreads();
    for (int st = 32; st; st >>= 1) {
        if (t < st) sm[t] = fmaxf(sm[t], sm[t + st]);
        __syncthreads();
    }
    float gmx = sm[0];
    float s = g_blksum[b * 64 + t] * expf(m - gmx);
    ss[t] = s; __syncthreads();
    for (int st = 32; st; st >>= 1) {
        if (t < st) ss[t] += ss[t + st];
        __syncthreads();
    }
    if (t == 0) { g_maxv[b] = gmx; g_invsum[b] = 1.f / ss[0]; }
}

// ---------------- normalize weights + partial context ----------------
#define DCH 256
__global__ void k_context(const float* __restrict__ value, float* __restrict__ out) {
    __shared__ float sw[DCH];
    __shared__ float4 red[256];
    int b  = blockIdx.x >> 5;
    int ch = blockIdx.x & 31;
    int s0 = ch * DCH;
    int t  = threadIdx.x;          // 256
    float mx = g_maxv[b], is = g_invsum[b];
    float* att = out + ATT_OFF + b * Ss;
    {
        int s = s0 + t;
        float w = expf(att[s] - mx) * is;
        att[s] = w;
        sw[t] = w;
    }
    __syncthreads();

    const int c4 = (t & 63) * 4;
    const int rg = t >> 6;
    const float* vb = value + ((long long)(b * Ss + s0 + rg * 64)) * Hh + c4;
    const float* swp = sw + rg * 64;

    float4 a = make_float4(0.f, 0.f, 0.f, 0.f);
#pragma unroll 4
    for (int r = 0; r < 64; ++r) {
        float w = swp[r];
        float4 v4 = __ldg((const float4*)(vb + (long long)r * Hh));
        a.x += w * v4.x; a.y += w * v4.y; a.z += w * v4.z; a.w += w * v4.w;
    }
    red[t] = a;
    __syncthreads();
    if (rg == 0) {
        float4 r1 = red[t + 64], r2 = red[t + 128], r3 = red[t + 192];
        a.x += r1.x + r2.x + r3.x;
        a.y += r1.y + r2.y + r3.y;
        a.z += r1.z + r2.z + r3.z;
        a.w += r1.w + r2.w + r3.w;
        *(float4*)(g_ctxpart + ((b * 32 + ch) * Hh + c4)) = a;
    }
}

__global__ void k_reduce_ctx(float* __restrict__ out) {
    int b = blockIdx.x, t = threadIdx.x;
    float s = 0.f;
#pragma unroll
    for (int c = 0; c < 32; ++c) s += g_ctxpart[(b * 32 + c) * Hh + t];
    out[b * Hh + t] = s;
}

// ---------------- launch ----------------
extern "C" void kernel_launch(void* const* d_in, const int* in_sizes, int n_in,
                              void* d_out, int out_size) {
    const float* query  = (const float*)d_in[0];
    const float* key    = (const float*)d_in[1];
    const float* value  = (const float*)d_in[2];
    const float* W_attn = (const float*)d_in[3];
    const float* b_attn = (const float*)d_in[4];
    const float* v      = (const float*)d_in[5];
    float* out = (float*)d_out;

    cudaFuncSetAttribute(k_scores_mma, cudaFuncAttributeMaxDynamicSharedMemorySize, SMEM_BYTES);

    k_prep<<<272, 256>>>(W_attn, query, b_attn);
    k_scores_mma<<<NCTA, 512, SMEM_BYTES>>>(key, v, out);
    k_softmax_combine<<<Bb, 64>>>();
    k_context<<<Bb * 32, 256>>>(value, out);
    k_reduce_ctx<<<Bb, Hh>>>(out);
}